// round 16
// baseline (speedup 1.0000x reference)
#include <cuda_runtime.h>
#include <cuda_fp16.h>
#include <cstdint>
#include <cstddef>

#define B_   32
#define DIN  64
#define DS   1024
#define L_   2048
#define PP   128     // p per block
#define TC   32      // timesteps per chunk
#define NC   (L_ / TC)
#define S2   36      // stage stride (floats), 16B-aligned rows
#define AS   72      // wsA row stride in halves (validated ldmatrix layout)
#define NSLOT 3

// pre-transposed input: g_ut[b][l][h] fp16 (8 MB), written by pre-kernel
__device__ __half g_ut[(size_t)B_ * L_ * DIN];

// dynamic smem layout (bytes)
#define STAGE_BYTES (NSLOT * PP * S2 * 4)    // 55296  stage[slot][p][t] fp32
#define WSA_BYTES   (2 * TC * AS * 2)        // 9216   wsA[par][l][h] fp16
#define WSB_BYTES   (PP * AS * 2)            // 18432  wsB[p][k] fp16
#define SMEM_TOTAL  (STAGE_BYTES + WSA_BYTES + WSB_BYTES)   // 82944 -> occ 2

#define BAR_SYNC(id, cnt) asm volatile("bar.sync %0, %1;" :: "r"(id), "r"(cnt) : "memory")
// ids: 1+s = FULL_PC[s] (256: P+C), 4+s = FULL_CW[s] (192: C+W), 10 = P fill (128)
// All barriers are rendezvous (both sides bar.sync) — validated deadlock-free.

__device__ __forceinline__ uint32_t sptr(const void* p) {
    return (uint32_t)__cvta_generic_to_shared(p);
}

// ---------------------------------------------------------------------------
// Pre-kernel: g_ut[b][l][h] = fp16(u[b][h][l])
// ---------------------------------------------------------------------------
__global__ __launch_bounds__(256)
void transpose_u(const float* __restrict__ u) {
    __shared__ float ts[DIN][33];
    const int b  = blockIdx.y;
    const int lc = blockIdx.x * 32;
    const int tid = threadIdx.x;
    const float* ub = u + (size_t)b * DIN * L_;
    #pragma unroll
    for (int k = 0; k < 8; k++) {
        int idx = tid + k * 256;
        int h = idx >> 5, l = idx & 31;
        ts[h][l] = ub[(size_t)h * L_ + lc + l];
    }
    __syncthreads();
    const int l  = tid >> 3;
    const int h0 = (tid & 7) * 8;
    __half2 p[4];
    #pragma unroll
    for (int j = 0; j < 4; j++)
        p[j] = __halves2half2(__float2half_rn(ts[h0 + 2 * j][l]),
                              __float2half_rn(ts[h0 + 2 * j + 1][l]));
    *(uint4*)(g_ut + ((size_t)b * L_ + lc + l) * DIN + h0) = *(uint4*)p;
}

// ---------------------------------------------------------------------------
// Fused: 4 P warps (MMA) -> 3-slot ring -> 4 C warps (chain) -> 2 W warps
// ---------------------------------------------------------------------------
__global__ __launch_bounds__(320, 2)
void esn_fused(const float* __restrict__ w_in,
               const float* __restrict__ w_hh,
               const float* __restrict__ bias,
               float* __restrict__ out) {
    extern __shared__ unsigned char smem_raw[];
    float*  stage = (float*)smem_raw;                                // [3][PP][S2]
    __half* wsA   = (__half*)(smem_raw + STAGE_BYTES);               // [2][TC][AS]
    __half* wsB   = (__half*)(smem_raw + STAGE_BYTES + WSA_BYTES);   // [PP][AS]

    const int tid = threadIdx.x;
    const int p0  = blockIdx.x * PP;
    const int b   = blockIdx.y;

    // wsB fill: wsB[p][k] = fp16(w_in[p0+p][k])
    for (int i = tid; i < PP * DIN; i += 320) {
        int p = i >> 6, k = i & 63;
        wsB[p * AS + k] = __float2half_rn(w_in[(size_t)(p0 + p) * DIN + k]);
    }
    __syncthreads();

    if (tid < 128) {
        // ===================== PRODUCERS (4 warps, m32 x n32) ==============
        const int warp = tid >> 5;           // n-tile: p cols [warp*32, +32)
        const int lane = tid & 31;
        const int g = lane >> 2, t = lane & 3;
        const __half* ut = g_ut + (size_t)b * L_ * DIN;

        // chunk-invariant B fragments: 4 kt x 4 n8 x 2 regs = 32
        uint32_t bfr[4][4][2];
        #pragma unroll
        for (int kt = 0; kt < 4; kt++)
            #pragma unroll
            for (int in = 0; in < 4; in++) {
                const __half* wp = wsB + (size_t)(warp * 32 + in * 8 + g) * AS + kt * 16 + 2 * t;
                bfr[kt][in][0] = *(const uint32_t*)(wp);
                bfr[kt][in][1] = *(const uint32_t*)(wp + 8);
            }

        // cp.async fill: 256 x 16B blocks per chunk; thread does blocks tid, tid+128
        const uint32_t wsa_base = sptr(wsA);
        #define ISSUE_FILL(c)                                                          \
        do {                                                                           \
            const int par_ = (c) & 1;                                                  \
            const __half* src_ = ut + (size_t)(c) * TC * DIN;                          \
            _Pragma("unroll")                                                          \
            for (int q_ = 0; q_ < 2; q_++) {                                           \
                int i_ = tid + q_ * 128;                                               \
                uint32_t dst_ = wsa_base + (uint32_t)(par_ * TC * AS + (i_ >> 3) * AS  \
                                + (i_ & 7) * 8) * 2;                                   \
                asm volatile("cp.async.cg.shared.global [%0], [%1], 16;"               \
                             :: "r"(dst_), "l"(src_ + i_ * 8));                        \
            }                                                                          \
        } while (0)

        const uint32_t lm_off = (uint32_t)((lane & 15) * AS) * 2 + ((lane >> 4) & 1) * 16;

        ISSUE_FILL(0);
        asm volatile("cp.async.commit_group;");

        for (int it = 0; it < NC; ++it) {
            const int par = it & 1;
            if (it + 1 < NC) ISSUE_FILL(it + 1);
            asm volatile("cp.async.commit_group;");
            asm volatile("cp.async.wait_group 1;");
            BAR_SYNC(10, 128);               // fills for chunk `it` visible

            float acc[2][4][4];
            #pragma unroll
            for (int im = 0; im < 2; im++)
                #pragma unroll
                for (int in = 0; in < 4; in++)
                    #pragma unroll
                    for (int q = 0; q < 4; q++) acc[im][in][q] = 0.f;

            const uint32_t abase = wsa_base + (uint32_t)(par * TC * AS) * 2 + lm_off;
            #pragma unroll
            for (int kt = 0; kt < 4; kt++) {
                uint32_t a[2][4];
                #pragma unroll
                for (int im = 0; im < 2; im++) {
                    const uint32_t addr = abase + (uint32_t)(im * 16 * AS) * 2 + kt * 32;
                    asm volatile(
                        "ldmatrix.sync.aligned.m8n8.x4.shared.b16 {%0,%1,%2,%3}, [%4];"
                        : "=r"(a[im][0]), "=r"(a[im][1]), "=r"(a[im][2]), "=r"(a[im][3])
                        : "r"(addr));
                }
                #pragma unroll
                for (int im = 0; im < 2; im++)
                    #pragma unroll
                    for (int in = 0; in < 4; in++)
                        asm volatile(
                            "mma.sync.aligned.m16n8k16.row.col.f32.f16.f16.f32 "
                            "{%0,%1,%2,%3}, {%4,%5,%6,%7}, {%8,%9}, {%0,%1,%2,%3};"
                            : "+f"(acc[im][in][0]), "+f"(acc[im][in][1]),
                              "+f"(acc[im][in][2]), "+f"(acc[im][in][3])
                            : "r"(a[im][0]), "r"(a[im][1]), "r"(a[im][2]), "r"(a[im][3]),
                              "r"(bfr[kt][in][0]), "r"(bfr[kt][in][1]));
            }

            // epilogue: D[m=l][n=p] -> stage[slot][p][t(=l)]  (banks 8t+g, CF)
            float* st = stage + (size_t)(it % NSLOT) * PP * S2;
            #pragma unroll
            for (int im = 0; im < 2; im++) {
                const int r0 = im * 16 + g;
                #pragma unroll
                for (int in = 0; in < 4; in++) {
                    const int c0 = warp * 32 + in * 8 + 2 * t;
                    st[(size_t)c0 * S2 + r0]           = acc[im][in][0];
                    st[(size_t)(c0 + 1) * S2 + r0]     = acc[im][in][1];
                    st[(size_t)c0 * S2 + r0 + 8]       = acc[im][in][2];
                    st[(size_t)(c0 + 1) * S2 + r0 + 8] = acc[im][in][3];
                }
            }
            BAR_SYNC(1 + it % NSLOT, 256);   // FULL_PC rendezvous (fence)
        }
    } else if (tid < 256) {
        // ===================== CHAIN WARPS (4, 128 chains) =================
        const int cp = tid - 128;            // p local
        const int p  = p0 + cp;
        const float d  = w_hh[(size_t)p * DS + p];
        const float hd = 0.5f * d;
        const float bi = bias[p];

        float x = 0.f;
        for (int c = 0; c < NC; ++c) {
            const int s = c % NSLOT;
            BAR_SYNC(1 + s, 256);            // wait pre[c]
            float* row = stage + (size_t)s * PP * S2 + (size_t)cp * S2;

            float upb[TC];
            #pragma unroll
            for (int k = 0; k < 8; k++) {
                float4 v = *(const float4*)(row + 4 * k);
                upb[4 * k]     = v.x + bi;
                upb[4 * k + 1] = v.y + bi;
                upb[4 * k + 2] = v.z + bi;
                upb[4 * k + 3] = v.w + bi;
            }

            // restructured chain: dependent path th -> FFMA(4) -> MUFU(16)
            //   z_{t+1} = 0.5d*th_t + (0.5d*x_{t-1} + upb[t+1])
            //   x_t     = 0.5*th_t + 0.5*x_{t-1}        (off critical path)
            float z = fmaf(x, d, upb[0]);
            #pragma unroll
            for (int kb = 0; kb < 8; kb++) {
                float xv[4];
                #pragma unroll
                for (int q = 0; q < 4; q++) {
                    const int t2 = kb * 4 + q;
                    float th;
                    asm("tanh.approx.f32 %0, %1;" : "=f"(th) : "f"(z));
                    float pre = (t2 < TC - 1) ? fmaf(hd, x, upb[t2 + 1]) : 0.f;
                    x = fmaf(0.5f, th, 0.5f * x);
                    z = fmaf(hd, th, pre);   // = d*x_new + upb[t2+1]
                    xv[q] = x;
                }
                *(float4*)(row + 4 * kb) = make_float4(xv[0], xv[1], xv[2], xv[3]);
            }
            BAR_SYNC(4 + s, 192);            // FULL_CW rendezvous (fence)
        }
    } else {
        // ===================== WRITER WARPS (2) ============================
        const int wt   = tid - 256;          // 0..63
        const int w    = wt >> 5;            // writer warp
        const int lane = wt & 31;
        const int rsub = lane >> 3;          // row within group of 4
        const int c4   = 4 * (lane & 7);     // t offset (float4)
        float* ob = out + (size_t)b * DS * L_;

        for (int c = 0; c < NC; ++c) {
            const int s = c % NSLOT;
            BAR_SYNC(4 + s, 192);            // wait x[c]
            const float* st = stage + (size_t)s * PP * S2;
            const int lc = c * TC;
            #pragma unroll
            for (int j = 0; j < 16; j++) {
                const int pr = w * 64 + j * 4 + rsub;     // covers 0..127
                float4 v = *(const float4*)(st + (size_t)pr * S2 + c4);
                __stcs((float4*)(ob + (size_t)(p0 + pr) * L_ + lc + c4), v);
            }
        }
    }
}

extern "C" void kernel_launch(void* const* d_in, const int* in_sizes, int n_in,
                              void* d_out, int out_size) {
    const float* u    = (const float*)d_in[0];  // [32, 64, 2048]
    const float* w_in = (const float*)d_in[1];  // [1024, 64]
    const float* w_hh = (const float*)d_in[2];  // [1024, 1024]
    const float* bias = (const float*)d_in[3];  // [1024]
    float* out = (float*)d_out;                 // [32, 1024, 2048]

    dim3 gt(L_ / 32, B_);
    transpose_u<<<gt, 256>>>(u);

    cudaFuncSetAttribute(esn_fused, cudaFuncAttributeMaxDynamicSharedMemorySize,
                         SMEM_TOTAL);
    dim3 g(DS / PP, B_);                        // 8 x 32 = 256 blocks, occ 2
    esn_fused<<<g, 320, SMEM_TOTAL>>>(w_in, w_hh, bias, out);
}

// round 17
// speedup vs baseline: 1.5204x; 1.5204x over previous
#include <cuda_runtime.h>
#include <cuda_fp16.h>
#include <cstdint>
#include <cstddef>

#define B_   32
#define DIN  64
#define DS   1024
#define L_   2048
#define PP   128     // p per block
#define TC   32      // timesteps per chunk
#define NC   (L_ / TC)
#define S2   36      // stage stride (floats), 16B-aligned rows
#define AS   72      // wsA row stride in halves (validated ldmatrix layout)
#define NSLOT 3

// pre-transposed input: g_ut[b][l][h] fp16 (8 MB), written by pre-kernel
__device__ __half g_ut[(size_t)B_ * L_ * DIN];

// dynamic smem layout (bytes)
#define STAGE_BYTES (NSLOT * PP * S2 * 4)    // 55296  stage[slot][p][t] fp32
#define WSA_BYTES   (2 * TC * AS * 2)        // 9216   wsA[par][l][h] fp16
#define WSB_BYTES   (PP * AS * 2)            // 18432  wsB[p][k] fp16
#define SMEM_TOTAL  (STAGE_BYTES + WSA_BYTES + WSB_BYTES)   // 82944 -> occ 2

#define BAR_SYNC(id, cnt) asm volatile("bar.sync %0, %1;" :: "r"(id), "r"(cnt) : "memory")
// ids: 1+s = FULL_PC[s] (256: P+C), 4+s = FULL_CW[s] (192: C+W), 10 = P fill (128)
// All barriers are rendezvous (both sides bar.sync) — validated deadlock-free.

__device__ __forceinline__ uint32_t sptr(const void* p) {
    return (uint32_t)__cvta_generic_to_shared(p);
}

// ---------------------------------------------------------------------------
// Pre-kernel: g_ut[b][l][h] = fp16(u[b][h][l])
// ---------------------------------------------------------------------------
__global__ __launch_bounds__(256)
void transpose_u(const float* __restrict__ u) {
    __shared__ float ts[DIN][33];
    const int b  = blockIdx.y;
    const int lc = blockIdx.x * 32;
    const int tid = threadIdx.x;
    const float* ub = u + (size_t)b * DIN * L_;
    #pragma unroll
    for (int k = 0; k < 8; k++) {
        int idx = tid + k * 256;
        int h = idx >> 5, l = idx & 31;
        ts[h][l] = ub[(size_t)h * L_ + lc + l];
    }
    __syncthreads();
    const int l  = tid >> 3;
    const int h0 = (tid & 7) * 8;
    __half2 p[4];
    #pragma unroll
    for (int j = 0; j < 4; j++)
        p[j] = __halves2half2(__float2half_rn(ts[h0 + 2 * j][l]),
                              __float2half_rn(ts[h0 + 2 * j + 1][l]));
    *(uint4*)(g_ut + ((size_t)b * L_ + lc + l) * DIN + h0) = *(uint4*)p;
}

// ---------------------------------------------------------------------------
// Fused: 4 P warps (MMA) -> 3-slot ring -> 4 C warps (chain) -> 2 W warps
// ---------------------------------------------------------------------------
__global__ __launch_bounds__(320, 2)
void esn_fused(const float* __restrict__ w_in,
               const float* __restrict__ w_hh,
               const float* __restrict__ bias,
               float* __restrict__ out) {
    extern __shared__ unsigned char smem_raw[];
    float*  stage = (float*)smem_raw;                                // [3][PP][S2]
    __half* wsA   = (__half*)(smem_raw + STAGE_BYTES);               // [2][TC][AS]
    __half* wsB   = (__half*)(smem_raw + STAGE_BYTES + WSA_BYTES);   // [PP][AS]

    const int tid = threadIdx.x;
    const int p0  = blockIdx.x * PP;
    const int b   = blockIdx.y;

    // wsB fill: wsB[p][k] = fp16(w_in[p0+p][k])
    for (int i = tid; i < PP * DIN; i += 320) {
        int p = i >> 6, k = i & 63;
        wsB[p * AS + k] = __float2half_rn(w_in[(size_t)(p0 + p) * DIN + k]);
    }
    __syncthreads();

    if (tid < 128) {
        // ===================== PRODUCERS (4 warps, m32 x n32) ==============
        const int warp = tid >> 5;           // n-tile: p cols [warp*32, +32)
        const int lane = tid & 31;
        const int g = lane >> 2, t = lane & 3;
        const __half* ut = g_ut + (size_t)b * L_ * DIN;

        // chunk-invariant B fragments: 4 kt x 4 n8 x 2 regs = 32
        uint32_t bfr[4][4][2];
        #pragma unroll
        for (int kt = 0; kt < 4; kt++)
            #pragma unroll
            for (int in = 0; in < 4; in++) {
                const __half* wp = wsB + (size_t)(warp * 32 + in * 8 + g) * AS + kt * 16 + 2 * t;
                bfr[kt][in][0] = *(const uint32_t*)(wp);
                bfr[kt][in][1] = *(const uint32_t*)(wp + 8);
            }

        // cp.async fill: 256 x 16B blocks per chunk; thread does blocks tid, tid+128
        const uint32_t wsa_base = sptr(wsA);
        #define ISSUE_FILL(c)                                                          \
        do {                                                                           \
            const int par_ = (c) & 1;                                                  \
            const __half* src_ = ut + (size_t)(c) * TC * DIN;                          \
            _Pragma("unroll")                                                          \
            for (int q_ = 0; q_ < 2; q_++) {                                           \
                int i_ = tid + q_ * 128;                                               \
                uint32_t dst_ = wsa_base + (uint32_t)(par_ * TC * AS + (i_ >> 3) * AS  \
                                + (i_ & 7) * 8) * 2;                                   \
                asm volatile("cp.async.cg.shared.global [%0], [%1], 16;"               \
                             :: "r"(dst_), "l"(src_ + i_ * 8));                        \
            }                                                                          \
        } while (0)

        const uint32_t lm_off = (uint32_t)((lane & 15) * AS) * 2 + ((lane >> 4) & 1) * 16;

        ISSUE_FILL(0);
        asm volatile("cp.async.commit_group;");

        for (int it = 0; it < NC; ++it) {
            const int par = it & 1;
            if (it + 1 < NC) ISSUE_FILL(it + 1);
            asm volatile("cp.async.commit_group;");
            asm volatile("cp.async.wait_group 1;");
            BAR_SYNC(10, 128);               // fills for chunk `it` visible

            float acc[2][4][4];
            #pragma unroll
            for (int im = 0; im < 2; im++)
                #pragma unroll
                for (int in = 0; in < 4; in++)
                    #pragma unroll
                    for (int q = 0; q < 4; q++) acc[im][in][q] = 0.f;

            const uint32_t abase = wsa_base + (uint32_t)(par * TC * AS) * 2 + lm_off;
            #pragma unroll
            for (int kt = 0; kt < 4; kt++) {
                uint32_t a[2][4];
                #pragma unroll
                for (int im = 0; im < 2; im++) {
                    const uint32_t addr = abase + (uint32_t)(im * 16 * AS) * 2 + kt * 32;
                    asm volatile(
                        "ldmatrix.sync.aligned.m8n8.x4.shared.b16 {%0,%1,%2,%3}, [%4];"
                        : "=r"(a[im][0]), "=r"(a[im][1]), "=r"(a[im][2]), "=r"(a[im][3])
                        : "r"(addr));
                }
                #pragma unroll
                for (int im = 0; im < 2; im++)
                    #pragma unroll
                    for (int in = 0; in < 4; in++)
                        asm volatile(
                            "mma.sync.aligned.m16n8k16.row.col.f32.f16.f16.f32 "
                            "{%0,%1,%2,%3}, {%4,%5,%6,%7}, {%8,%9}, {%0,%1,%2,%3};"
                            : "+f"(acc[im][in][0]), "+f"(acc[im][in][1]),
                              "+f"(acc[im][in][2]), "+f"(acc[im][in][3])
                            : "r"(a[im][0]), "r"(a[im][1]), "r"(a[im][2]), "r"(a[im][3]),
                              "r"(bfr[kt][in][0]), "r"(bfr[kt][in][1]));
            }

            // epilogue: D[m=l][n=p] -> stage[slot][p][t(=l)]  (banks 8t+g, CF)
            float* st = stage + (size_t)(it % NSLOT) * PP * S2;
            #pragma unroll
            for (int im = 0; im < 2; im++) {
                const int r0 = im * 16 + g;
                #pragma unroll
                for (int in = 0; in < 4; in++) {
                    const int c0 = warp * 32 + in * 8 + 2 * t;
                    st[(size_t)c0 * S2 + r0]           = acc[im][in][0];
                    st[(size_t)(c0 + 1) * S2 + r0]     = acc[im][in][1];
                    st[(size_t)c0 * S2 + r0 + 8]       = acc[im][in][2];
                    st[(size_t)(c0 + 1) * S2 + r0 + 8] = acc[im][in][3];
                }
            }
            BAR_SYNC(1 + it % NSLOT, 256);   // FULL_PC rendezvous (fence)
        }
    } else if (tid < 256) {
        // ===================== CHAIN WARPS (4, 128 chains) =================
        const int cp = tid - 128;            // p local
        const int p  = p0 + cp;
        const float d  = w_hh[(size_t)p * DS + p];
        const float hd = 0.5f * d;
        const float bi = bias[p];

        float x = 0.f;
        for (int c = 0; c < NC; ++c) {
            const int s = c % NSLOT;
            BAR_SYNC(1 + s, 256);            // wait pre[c]
            float* row = stage + (size_t)s * PP * S2 + (size_t)cp * S2;

            float upb[TC];
            #pragma unroll
            for (int k = 0; k < 8; k++) {
                float4 v = *(const float4*)(row + 4 * k);
                upb[4 * k]     = v.x + bi;
                upb[4 * k + 1] = v.y + bi;
                upb[4 * k + 2] = v.z + bi;
                upb[4 * k + 3] = v.w + bi;
            }

            // restructured chain: dependent path th -> FFMA(4) -> MUFU(16)
            //   z_{t+1} = 0.5d*th_t + (0.5d*x_{t-1} + upb[t+1])
            //   x_t     = 0.5*th_t + 0.5*x_{t-1}        (off critical path)
            float z = fmaf(x, d, upb[0]);
            #pragma unroll
            for (int kb = 0; kb < 8; kb++) {
                float xv[4];
                #pragma unroll
                for (int q = 0; q < 4; q++) {
                    const int t2 = kb * 4 + q;
                    float th;
                    asm("tanh.approx.f32 %0, %1;" : "=f"(th) : "f"(z));
                    float pre = (t2 < TC - 1) ? fmaf(hd, x, upb[t2 + 1]) : 0.f;
                    x = fmaf(0.5f, th, 0.5f * x);
                    z = fmaf(hd, th, pre);   // = d*x_new + upb[t2+1]
                    xv[q] = x;
                }
                *(float4*)(row + 4 * kb) = make_float4(xv[0], xv[1], xv[2], xv[3]);
            }
            BAR_SYNC(4 + s, 192);            // FULL_CW rendezvous (fence)
        }
    } else {
        // ===================== WRITER WARPS (2) ============================
        const int wt   = tid - 256;          // 0..63
        const int w    = wt >> 5;            // writer warp
        const int lane = wt & 31;
        const int rsub = lane >> 3;          // row within group of 4
        const int c4   = 4 * (lane & 7);     // t offset (float4)
        float* ob = out + (size_t)b * DS * L_;

        for (int c = 0; c < NC; ++c) {
            const int s = c % NSLOT;
            BAR_SYNC(4 + s, 192);            // wait x[c]
            const float* st = stage + (size_t)s * PP * S2;
            const int lc = c * TC;
            #pragma unroll
            for (int j = 0; j < 16; j++) {
                const int pr = w * 64 + j * 4 + rsub;     // covers 0..127
                float4 v = *(const float4*)(st + (size_t)pr * S2 + c4);
                __stcs((float4*)(ob + (size_t)(p0 + pr) * L_ + lc + c4), v);
            }
        }
    }
}

extern "C" void kernel_launch(void* const* d_in, const int* in_sizes, int n_in,
                              void* d_out, int out_size) {
    const float* u    = (const float*)d_in[0];  // [32, 64, 2048]
    const float* w_in = (const float*)d_in[1];  // [1024, 64]
    const float* w_hh = (const float*)d_in[2];  // [1024, 1024]
    const float* bias = (const float*)d_in[3];  // [1024]
    float* out = (float*)d_out;                 // [32, 1024, 2048]

    dim3 gt(L_ / 32, B_);
    transpose_u<<<gt, 256>>>(u);

    cudaFuncSetAttribute(esn_fused, cudaFuncAttributeMaxDynamicSharedMemorySize,
                         SMEM_TOTAL);
    dim3 g(DS / PP, B_);                        // 8 x 32 = 256 blocks, occ 2
    esn_fused<<<g, 320, SMEM_TOTAL>>>(w_in, w_hh, bias, out);
}